// round 5
// baseline (speedup 1.0000x reference)
#include <cuda_runtime.h>

// Uniform cubic B-spline via per-interval monomial (Horner) form.
// t = (x+1)*31.5, j = trunc(t) (clamped to 62), u = t-j,
// out = p0[j] + u*(p1[j] + u*(p2[j] + u*p3[j])), where
//   p0=(c0+4c1+c2)/6, p1=(c2-c0)/2, p2=(c0-2c1+c2)/2, p3=(c3-c0+3(c1-c2))/6.
// Table replicated 8x across the eight 16B shared bank groups ->
// every LDS.128 quarter-warp phase is conflict-free for random j.
//
// R5: occupancy push. 8 CTAs/SM (forced via launch_bounds), grid = one exact
// wave of 1184, MLP=2 so the schedule fits in 32 registers.

#define REP 8
#define NTBL 63

__device__ __forceinline__ float eval_one(float x, const float4* __restrict__ tp) {
    float t = fmaf(x, 31.5f, 31.5f);
    int j = (int)t;                  // t >= 0: truncation == floor
    j = min(j, 62);                  // guard t rounding up to 63.0
    float u = t - (float)j;
    float4 p = tp[j * REP];          // tp pre-offset by lane's bank-group
    return fmaf(fmaf(fmaf(p.w, u, p.z), u, p.y), u, p.x);
}

__device__ __forceinline__ float4 eval_four(float4 xv, const float4* __restrict__ tp) {
    float4 ov;
    ov.x = eval_one(xv.x, tp);
    ov.y = eval_one(xv.y, tp);
    ov.z = eval_one(xv.z, tp);
    ov.w = eval_one(xv.w, tp);
    return ov;
}

__global__ void __launch_bounds__(256, 8)
bspline_kernel(const float4* __restrict__ x4,
               const float* __restrict__ coeffs,
               float4* __restrict__ o4, int n4) {
    __shared__ float4 tbl[NTBL * REP];
    int tid = threadIdx.x;
    #pragma unroll
    for (int e = tid; e < NTBL * REP; e += 256) {
        int j = e >> 3;
        float c0 = __ldg(coeffs + j);
        float c1 = __ldg(coeffs + j + 1);
        float c2 = __ldg(coeffs + j + 2);
        float c3 = __ldg(coeffs + j + 3);
        float4 p;
        p.x = fmaf(4.0f, c1, c0 + c2) * 0.16666666666666666f;
        p.y = (c2 - c0) * 0.5f;
        p.z = fmaf(-2.0f, c1, c0 + c2) * 0.5f;
        p.w = fmaf(3.0f, c1 - c2, c3 - c0) * 0.16666666666666666f;
        tbl[e] = p;
    }
    __syncthreads();

    const float4* __restrict__ tp = tbl + (tid & (REP - 1));
    const int stride = gridDim.x * blockDim.x;
    int i = blockIdx.x * blockDim.x + tid;

    // MLP=2 main loop: two independent float4 loads in flight,
    // fits the 32-register budget at 8 CTAs/SM.
    for (; i + stride < n4; i += 2 * stride) {
        float4 xa = x4[i];
        float4 xb = x4[i + stride];
        o4[i]          = eval_four(xa, tp);
        o4[i + stride] = eval_four(xb, tp);
    }
    if (i < n4) {
        float4 xa = x4[i];
        o4[i] = eval_four(xa, tp);
    }
}

extern "C" void kernel_launch(void* const* d_in, const int* in_sizes, int n_in,
                              void* d_out, int out_size) {
    const float* x      = (const float*)d_in[0];
    const float* coeffs = (const float*)d_in[1];
    float* out = (float*)d_out;
    int n  = in_sizes[0];
    int n4 = n >> 2;                 // N = 2^22, divisible by 4
    int threads = 256;
    int blocks  = 1184;              // 8 CTAs/SM x 148 SMs = one exact wave
    int max_blocks = (n4 + threads - 1) / threads;
    if (blocks > max_blocks) blocks = max_blocks;
    if (blocks < 1) blocks = 1;
    bspline_kernel<<<blocks, threads>>>((const float4*)x, coeffs, (float4*)out, n4);
}